// round 6
// baseline (speedup 1.0000x reference)
#include <cuda_runtime.h>

// IntraAgg, R6:
//   Kernel 1 (norm_kernel): invnorm[n] = rsqrt(|features[n]|^2) for all nodes,
//     stored in a __device__ global (each node's norm was being recomputed ~10x
//     across the batch; ALU pipe was 43% and nothing else saturated).
//   Kernel 2 (intra_agg_kernel): one warp per batch row, lane = float4 chunk.
//     32 center-dot-neighbor dots -> ONE 32-slot transpose reduction (31 shfl,
//     the minimum) -> score = dot * invnorm[neigh] -> REDUX top-ns -> mean+relu.
//   All address math 32-bit (table is 51.2MB), neighbor indices via int4 loads.

#define FULLM 0xffffffffu
#define K_NEIGH 32
#define CAP_NODES 131072

__device__ float g_invn[CAP_NODES];

__global__ __launch_bounds__(256)
void norm_kernel(const float* __restrict__ features, int n_nodes)
{
    const int w    = (blockIdx.x * blockDim.x + threadIdx.x) >> 5;
    const int lane = threadIdx.x & 31;
    if (w >= n_nodes) return;
    const float4* __restrict__ f4 = reinterpret_cast<const float4*>(features);
    const float4 v = __ldg(&f4[w * 32 + lane]);
    float s = v.x * v.x + v.y * v.y + v.z * v.z + v.w * v.w;
    #pragma unroll
    for (int o = 16; o; o >>= 1) s += __shfl_xor_sync(FULLM, s, o);
    if (lane == 0) g_invn[w] = rsqrtf(s);
}

__global__ __launch_bounds__(256)
void intra_agg_kernel(const float* __restrict__ features,
                      const int*   __restrict__ nodes,
                      const int*   __restrict__ neighs,
                      const int*   __restrict__ nsp,   // may be null
                      float*       __restrict__ out,
                      int B)
{
    const int warp = (blockIdx.x * blockDim.x + threadIdx.x) >> 5;
    const int lane = threadIdx.x & 31;
    if (warp >= B) return;
    const int b = warp;

    int ns = (nsp != nullptr) ? __ldg(nsp) : 10;
    ns = min(max(ns, 1), K_NEIGH);

    const float4* __restrict__ f4   = reinterpret_cast<const float4*>(features);
    const int*    __restrict__ nrow = neighs + b * K_NEIGH;

    // Lane k owns neighbor k's score: gather its inverse norm up front
    // (coalesced index load + one scattered 4B gather from the hot 400KB table).
    const int   myIdx = __ldg(&nrow[lane]);
    const float myInv = __ldg(&g_invn[myIdx]);

    const int   node = __ldg(&nodes[b]);
    const float4 c4  = __ldg(&f4[node * 32 + lane]);

    // ---------------- Phase 1: 32 partial dots, batched loads (MLP=8) ------
    const int4* __restrict__ n4 = reinterpret_cast<const int4*>(nrow);
    float pv[32];
    #pragma unroll
    for (int j0 = 0; j0 < 32; j0 += 8) {
        const int4 qa = __ldg(&n4[j0 / 4]);
        const int4 qb = __ldg(&n4[j0 / 4 + 1]);
        const int r[8] = {qa.x, qa.y, qa.z, qa.w, qb.x, qb.y, qb.z, qb.w};
        float4 v[8];
        #pragma unroll
        for (int j = 0; j < 8; ++j)
            v[j] = __ldg(&f4[r[j] * 32 + lane]);
        #pragma unroll
        for (int j = 0; j < 8; ++j)
            pv[j0 + j] = c4.x * v[j].x + c4.y * v[j].y
                       + c4.z * v[j].z + c4.w * v[j].w;
    }

    // 32-slot transpose-reduction: 16+8+4+2+1 = 31 shuffles; lane l ends
    // holding the complete dot for neighbor l in pv[0].
    #pragma unroll
    for (int o = 16; o >= 1; o >>= 1) {
        #pragma unroll
        for (int j = 0; j < o; ++j) {
            const float send = (lane & o) ? pv[j] : pv[j + o];
            const float recv = __shfl_xor_sync(FULLM, send, o);
            pv[j] = ((lane & o) ? pv[j + o] : pv[j]) + recv;
        }
    }
    const float score = pv[0] * myInv;   // cosine ranking (c-norm drops out)

    // ---------------- Phase 2: top-ns selection (set only) -----------------
    unsigned u = __float_as_uint(score);
    u = (u & 0x80000000u) ? ~u : (u | 0x80000000u);   // monotonic f32->u32

    unsigned sel = 0u;
    for (int i = 0; i < ns; ++i) {
        unsigned v   = ((sel >> lane) & 1u) ? 0u : u;
        unsigned m   = __reduce_max_sync(FULLM, v);
        unsigned bal = __ballot_sync(FULLM, v == m);
        sel |= 1u << (__ffs(bal) - 1);                // lowest index on ties
    }

    // ---------------- Phase 3: mean of selected rows + relu ----------------
    float ax = 0.f, ay = 0.f, az = 0.f, aw = 0.f;
    unsigned rem = sel;
    #pragma unroll 5
    for (int i = 0; i < ns; ++i) {
        const int k = __ffs(rem) - 1;
        rem &= rem - 1;
        const int rI = __ldg(&nrow[k]);               // uniform, L1-hot
        const float4 v = __ldg(&f4[rI * 32 + lane]);
        ax += v.x; ay += v.y; az += v.z; aw += v.w;
    }
    const float inv = 1.0f / (float)ns;
    float4 o;
    o.x = fmaxf(ax * inv, 0.0f);
    o.y = fmaxf(ay * inv, 0.0f);
    o.z = fmaxf(az * inv, 0.0f);
    o.w = fmaxf(aw * inv, 0.0f);
    reinterpret_cast<float4*>(out)[b * 32 + lane] = o;
}

extern "C" void kernel_launch(void* const* d_in, const int* in_sizes, int n_in,
                              void* d_out, int out_size)
{
    const float* features = (const float*)d_in[0];
    const int*   nodes    = (const int*)d_in[1];
    const int*   neighs   = (const int*)d_in[2];
    const int*   nsp      = (n_in > 3) ? (const int*)d_in[3] : nullptr;

    int n_nodes = in_sizes[0] / 128;           // features element count / D
    if (n_nodes > CAP_NODES) n_nodes = CAP_NODES;
    const int B = in_sizes[1];                 // nodes element count = batch

    const int threads = 256;                   // 8 warps per block
    const int nb_norm = (n_nodes + 7) / 8;
    norm_kernel<<<nb_norm, threads>>>(features, n_nodes);

    const int nb_main = (B + 7) / 8;
    intra_agg_kernel<<<nb_main, threads>>>(features, nodes, neighs, nsp,
                                           (float*)d_out, B);
}